// round 5
// baseline (speedup 1.0000x reference)
#include <cuda_runtime.h>
#include <cuda_bf16.h>
#include <math.h>
#include <stdint.h>

// Problem constants (fixed by reference)
#define NNODES 100000
#define DFEAT  128
#define EMAX   1600000
#define ALPHA_C 0.1f
#define LMAX   8

#define HS_STRIDE_F 132   // floats per Hs row (128 + 4 pad) -> conflict-free frag reads
#define WS_STRIDE   18    // float2 per Ws n-row (16 + 2 pad)
#define SMEM_BYTES  (128 * HS_STRIDE_F * 4 + 128 * WS_STRIDE * 8)   // 67584 + 18432 = 86016

// ---------------- scratch (device globals; no allocation allowed) ----------------
// ping-pong layer buffers per graph (fused kernel must NOT update in place:
// other blocks gather-read arbitrary rows of the layer input while we write)
__device__ float  g_bufA1[NNODES * DFEAT];
__device__ float  g_bufB1[NNODES * DFEAT];
__device__ float  g_bufA2[NNODES * DFEAT];
__device__ float  g_bufB2[NNODES * DFEAT];
__device__ float2 g_wp2[LMAX * DFEAT * DFEAT];   // [l][n][k] = (hi, lo) of W'[k][n]
__device__ int    g_col1[EMAX];
__device__ int    g_col2[EMAX];
__device__ int    g_deg1[NNODES];
__device__ int    g_deg2[NNODES];
__device__ int    g_rowptr1[NNODES + 1];
__device__ int    g_rowptr2[NNODES + 1];
__device__ int    g_cursor1[NNODES];
__device__ int    g_cursor2[NNODES];
__device__ float  g_norm1[NNODES];
__device__ float  g_norm2[NNODES];
__device__ double g_sum[256];    // [graph*128 + col]
__device__ double g_sumsq[256];
__device__ float  g_mean[256];
__device__ float  g_rstd[256];

// ---------------- setup kernels ----------------

__global__ void zero_kernel(int* d1, int* d2, double* s, double* s2, int n) {
    int i = blockIdx.x * blockDim.x + threadIdx.x;
    if (i < n) { d1[i] = 0; d2[i] = 0; }
    if (i < 256) { s[i] = 0.0; s2[i] = 0.0; }
}

__global__ void hist2_kernel(const int* __restrict__ dstA, int* __restrict__ degA, int EA,
                             const int* __restrict__ dstB, int* __restrict__ degB, int EB) {
    const int* dst = blockIdx.y ? dstB : dstA;
    int*       deg = blockIdx.y ? degB : degA;
    int        E   = blockIdx.y ? EB : EA;
    int i = blockIdx.x * blockDim.x + threadIdx.x;
    if (i < E) atomicAdd(&deg[dst[i]], 1);
}

// fast single-block-per-graph scan: 1024 threads, 4 elems/thread, warp-shuffle scan.
__global__ __launch_bounds__(1024) void scan2_kernel(
    const int* __restrict__ degA, int* __restrict__ rpA, int* __restrict__ curA, float* __restrict__ normA,
    const int* __restrict__ degB, int* __restrict__ rpB, int* __restrict__ curB, float* __restrict__ normB,
    int n)
{
    const int* deg  = blockIdx.x ? degB  : degA;
    int*       rp   = blockIdx.x ? rpB   : rpA;
    int*       cur  = blockIdx.x ? curB  : curA;
    float*     norm = blockIdx.x ? normB : normA;

    __shared__ int wsum[32];
    __shared__ int s_carry;
    int tid = threadIdx.x, lane = tid & 31, wid = tid >> 5;
    if (tid == 0) s_carry = 0;
    __syncthreads();

    for (int base = 0; base < n; base += 4096) {
        int idx = base + tid * 4;
        int v0 = (idx + 0 < n) ? deg[idx + 0] : 0;
        int v1 = (idx + 1 < n) ? deg[idx + 1] : 0;
        int v2 = (idx + 2 < n) ? deg[idx + 2] : 0;
        int v3 = (idx + 3 < n) ? deg[idx + 3] : 0;
        int p0 = v0, p1 = p0 + v1, p2 = p1 + v2, p3 = p2 + v3;
        int tot = p3;
        #pragma unroll
        for (int off = 1; off < 32; off <<= 1) {
            int t = __shfl_up_sync(0xFFFFFFFFu, tot, off);
            if (lane >= off) tot += t;
        }
        if (lane == 31) wsum[wid] = tot;
        __syncthreads();
        if (wid == 0) {
            int w = wsum[lane];
            #pragma unroll
            for (int off = 1; off < 32; off <<= 1) {
                int t = __shfl_up_sync(0xFFFFFFFFu, w, off);
                if (lane >= off) w += t;
            }
            wsum[lane] = w;
        }
        __syncthreads();
        int carry = s_carry;
        int excl = carry + (wid ? wsum[wid - 1] : 0) + (tot - p3);
        if (idx + 0 < n) { rp[idx + 0] = excl;      cur[idx + 0] = excl;      norm[idx + 0] = rsqrtf(fmaxf((float)v0, 1.f)); }
        if (idx + 1 < n) { rp[idx + 1] = excl + p0; cur[idx + 1] = excl + p0; norm[idx + 1] = rsqrtf(fmaxf((float)v1, 1.f)); }
        if (idx + 2 < n) { rp[idx + 2] = excl + p1; cur[idx + 2] = excl + p1; norm[idx + 2] = rsqrtf(fmaxf((float)v2, 1.f)); }
        if (idx + 3 < n) { rp[idx + 3] = excl + p2; cur[idx + 3] = excl + p2; norm[idx + 3] = rsqrtf(fmaxf((float)v3, 1.f)); }
        __syncthreads();
        if (tid == 0) s_carry = carry + wsum[31];
        __syncthreads();
    }
    if (tid == 0) rp[n] = s_carry;
}

__global__ void fill2_kernel(const int* __restrict__ srcA, const int* __restrict__ dstA,
                             int* __restrict__ curA, int* __restrict__ colA, int EA,
                             const int* __restrict__ srcB, const int* __restrict__ dstB,
                             int* __restrict__ curB, int* __restrict__ colB, int EB) {
    const int* src = blockIdx.y ? srcB : srcA;
    const int* dst = blockIdx.y ? dstB : dstA;
    int* cursor    = blockIdx.y ? curB : curA;
    int* col       = blockIdx.y ? colB : colA;
    int  E         = blockIdx.y ? EB : EA;
    int i = blockIdx.x * blockDim.x + threadIdx.x;
    if (i < E) {
        int d = dst[i];
        int p = atomicAdd(&cursor[d], 1);
        col[p] = src[i];
    }
}

// W' = (1-beta)*I + beta*W, split into tf32 hi/lo, stored transposed [n][k]
__global__ void wprime2_kernel(const float* __restrict__ W, float2* __restrict__ Wp2) {
    int l = blockIdx.y;
    int i = blockIdx.x * blockDim.x + threadIdx.x;   // 0..16383
    if (i >= DFEAT * DFEAT) return;
    float beta = logf(1.0f / (float)(l + 1) + 1.0f); // LAMBDA = 1
    int n = i >> 7, k = i & 127;
    float v = beta * W[l * DFEAT * DFEAT + k * DFEAT + n];
    if (k == n) v += 1.0f - beta;
    float hi = __uint_as_float(__float_as_uint(v) & 0xFFFFE000u);
    float lo = v - hi;
    Wp2[l * DFEAT * DFEAT + i] = make_float2(hi, lo);
}

// ---------------- fused layer kernel ----------------
// Phase A: aggregate 128 dst rows into smem Hs (fp32):
//   Hs[r] = (1-ALPHA)*norm[r]*sum_{e} norm[src]*feat[src] + ALPHA*feat0[r]
// Phase B: out = relu(Hs @ W' + bias) via 3xTF32 mma (hi/lo split of Hs on the fly).
// NOTE: out must NOT alias feat (other blocks gather-read feat rows concurrently).

__device__ __forceinline__ void mma_tf32(float c[4], const uint32_t a[4],
                                         uint32_t b0, uint32_t b1) {
    asm volatile(
        "mma.sync.aligned.m16n8k8.row.col.f32.tf32.tf32.f32 "
        "{%0,%1,%2,%3}, {%4,%5,%6,%7}, {%8,%9}, {%0,%1,%2,%3};\n"
        : "+f"(c[0]), "+f"(c[1]), "+f"(c[2]), "+f"(c[3])
        : "r"(a[0]), "r"(a[1]), "r"(a[2]), "r"(a[3]), "r"(b0), "r"(b1));
}

__device__ __forceinline__ float tf32_hi(float v) {
    return __uint_as_float(__float_as_uint(v) & 0xFFFFE000u);
}

extern __shared__ float smem_dyn[];

__global__ __launch_bounds__(256, 2) void layer_fused_kernel(
    const float* __restrict__ fA, const float* __restrict__ f0A, const float* __restrict__ nmA,
    const int* __restrict__ rpA, const int* __restrict__ colA, float* __restrict__ outA,
    const float* __restrict__ fB, const float* __restrict__ f0B, const float* __restrict__ nmB,
    const int* __restrict__ rpB, const int* __restrict__ colB, float* __restrict__ outB,
    const float2* __restrict__ Wp2, const float* __restrict__ bias, int n)
{
    const float* feat  = blockIdx.y ? fB  : fA;
    const float* feat0 = blockIdx.y ? f0B : f0A;
    const float* norm  = blockIdx.y ? nmB : nmA;
    const int*   rowptr= blockIdx.y ? rpB : rpA;
    const int*   col   = blockIdx.y ? colB: colA;
    float*       out   = blockIdx.y ? outB : outA;

    float*  Hs = smem_dyn;                                   // [128][HS_STRIDE_F]
    float2* Ws = (float2*)(smem_dyn + 128 * HS_STRIDE_F);    // [128][WS_STRIDE]

    const int tid  = threadIdx.x;
    const int wid  = tid >> 5;
    const int lane = tid & 31;
    const int blockRow = blockIdx.x * 128;

    // ================= Phase A: aggregate into Hs =================
    // 8 warps x 16 rows each, warp-per-row, lane owns 4 columns.
    for (int rr = 0; rr < 16; rr++) {
        int r = wid * 16 + rr;
        int grow = blockRow + r;
        float4 o = make_float4(0.f, 0.f, 0.f, 0.f);
        if (grow < n) {
            int e0 = __ldg(&rowptr[grow]);
            int e1 = __ldg(&rowptr[grow + 1]);
            float4 acc = make_float4(0.f, 0.f, 0.f, 0.f);
            int e = e0;
            // unroll by 4 for MLP
            for (; e + 3 < e1; e += 4) {
                int s0 = __ldg(&col[e]);
                int s1 = __ldg(&col[e + 1]);
                int s2 = __ldg(&col[e + 2]);
                int s3 = __ldg(&col[e + 3]);
                float n0 = __ldg(&norm[s0]);
                float n1 = __ldg(&norm[s1]);
                float n2 = __ldg(&norm[s2]);
                float n3 = __ldg(&norm[s3]);
                float4 v0 = __ldg((const float4*)&feat[s0 * DFEAT + lane * 4]);
                float4 v1 = __ldg((const float4*)&feat[s1 * DFEAT + lane * 4]);
                float4 v2 = __ldg((const float4*)&feat[s2 * DFEAT + lane * 4]);
                float4 v3 = __ldg((const float4*)&feat[s3 * DFEAT + lane * 4]);
                acc.x += n0 * v0.x + n1 * v1.x + n2 * v2.x + n3 * v3.x;
                acc.y += n0 * v0.y + n1 * v1.y + n2 * v2.y + n3 * v3.y;
                acc.z += n0 * v0.z + n1 * v1.z + n2 * v2.z + n3 * v3.z;
                acc.w += n0 * v0.w + n1 * v1.w + n2 * v2.w + n3 * v3.w;
            }
            for (; e < e1; e++) {
                int s0 = __ldg(&col[e]);
                float n0 = __ldg(&norm[s0]);
                float4 v0 = __ldg((const float4*)&feat[s0 * DFEAT + lane * 4]);
                acc.x += n0 * v0.x; acc.y += n0 * v0.y;
                acc.z += n0 * v0.z; acc.w += n0 * v0.w;
            }
            float scale = (1.0f - ALPHA_C) * __ldg(&norm[grow]);
            float4 f0v = __ldg((const float4*)&feat0[grow * DFEAT + lane * 4]);
            o.x = scale * acc.x + ALPHA_C * f0v.x;
            o.y = scale * acc.y + ALPHA_C * f0v.y;
            o.z = scale * acc.z + ALPHA_C * f0v.z;
            o.w = scale * acc.w + ALPHA_C * f0v.w;
        }
        float* dst = &Hs[r * HS_STRIDE_F + lane * 4];
        dst[0] = o.x; dst[1] = o.y; dst[2] = o.z; dst[3] = o.w;
    }
    __syncthreads();

    // ================= Phase B: 3xTF32 GEMM from Hs =================
    const int g  = lane >> 2;     // 0..7
    const int tg = lane & 3;      // 0..3
    const int warpM = wid & 1;    // 2 over M: 64 rows each
    const int warpN = wid >> 1;   // 4 over N: 32 cols each
    const int M0w = warpM * 64;
    const int N0w = warpN * 32;

    float c[4][4][4];   // [mt][nt][frag]
    #pragma unroll
    for (int mt = 0; mt < 4; mt++)
        #pragma unroll
        for (int nt = 0; nt < 4; nt++)
            #pragma unroll
            for (int q = 0; q < 4; q++) c[mt][nt][q] = 0.f;

    for (int stage = 0; stage < 8; stage++) {
        const int ks0 = stage * 16;
        // fill Ws tile: 128 n x 16 k float2 (pre-split) = 1024 float4
        #pragma unroll
        for (int it = 0; it < 4; it++) {
            int f = tid + it * 256;          // 0..1023
            int nn = f >> 3;
            int q = f & 7;                   // 8 float4 per n-row
            float4 v = *(const float4*)&Wp2[nn * DFEAT + ks0 + q * 2];
            *(float4*)&Ws[nn * WS_STRIDE + q * 2] = v;
        }
        __syncthreads();

        #pragma unroll
        for (int ks = 0; ks < 2; ks++) {
            const int K0 = ks0 + ks * 8;     // absolute k into Hs
            // A frags (hi/lo) for 4 M-tiles from fp32 Hs, split on the fly
            uint32_t ah[4][4], al[4][4];
            #pragma unroll
            for (int mt = 0; mt < 4; mt++) {
                int base = (M0w + mt * 16 + g) * HS_STRIDE_F + K0 + tg;
                float v0 = Hs[base];                       // (row g,   k tg)
                float v1 = Hs[base + 8 * HS_STRIDE_F];     // (row g+8, k tg)
                float v2 = Hs[base + 4];                   // (row g,   k tg+4)
                float v3 = Hs[base + 8 * HS_STRIDE_F + 4];
                float h0 = tf32_hi(v0), h1 = tf32_hi(v1), h2 = tf32_hi(v2), h3 = tf32_hi(v3);
                ah[mt][0] = __float_as_uint(h0); al[mt][0] = __float_as_uint(v0 - h0);
                ah[mt][1] = __float_as_uint(h1); al[mt][1] = __float_as_uint(v1 - h1);
                ah[mt][2] = __float_as_uint(h2); al[mt][2] = __float_as_uint(v2 - h2);
                ah[mt][3] = __float_as_uint(h3); al[mt][3] = __float_as_uint(v3 - h3);
            }
            // B frags (pre-split) for 4 N-tiles
            uint32_t bh[4][2], bl[4][2];
            #pragma unroll
            for (int nt = 0; nt < 4; nt++) {
                int base = (N0w + nt * 8 + g) * WS_STRIDE + ks * 8 + tg;
                float2 v0 = Ws[base];      // b0: (k tg,   n g)
                float2 v1 = Ws[base + 4];  // b1: (k tg+4, n g)
                bh[nt][0] = __float_as_uint(v0.x); bl[nt][0] = __float_as_uint(v0.y);
                bh[nt][1] = __float_as_uint(v1.x); bl[nt][1] = __float_as_uint(v1.y);
            }
            #pragma unroll
            for (int mt = 0; mt < 4; mt++)
                #pragma unroll
                for (int nt = 0; nt < 4; nt++) {
                    mma_tf32(c[mt][nt], ah[mt], bh[nt][0], bh[nt][1]);
                    mma_tf32(c[mt][nt], ah[mt], bl[nt][0], bl[nt][1]);
                    mma_tf32(c[mt][nt], al[mt], bh[nt][0], bh[nt][1]);
                }
        }
        __syncthreads();
    }

    // epilogue: relu(c + bias)
    #pragma unroll
    for (int mt = 0; mt < 4; mt++) {
        int row0 = blockRow + M0w + mt * 16 + g;
        int row1 = row0 + 8;
        #pragma unroll
        for (int nt = 0; nt < 4; nt++) {
            int colj = N0w + nt * 8 + 2 * tg;
            float2 bv = *(const float2*)&bias[colj];
            if (row0 < n) {
                float2 o0;
                o0.x = fmaxf(c[mt][nt][0] + bv.x, 0.f);
                o0.y = fmaxf(c[mt][nt][1] + bv.y, 0.f);
                *(float2*)&out[row0 * DFEAT + colj] = o0;
            }
            if (row1 < n) {
                float2 o1;
                o1.x = fmaxf(c[mt][nt][2] + bv.x, 0.f);
                o1.y = fmaxf(c[mt][nt][3] + bv.y, 0.f);
                *(float2*)&out[row1 * DFEAT + colj] = o1;
            }
        }
    }
}

// ---------------- stats / output kernels ----------------

__global__ void colstats2_kernel(const float* __restrict__ fA, const float* __restrict__ fB,
                                 double* __restrict__ sum, double* __restrict__ sumsq, int n) {
    const float* f = blockIdx.y ? fB : fA;
    int soff = blockIdx.y * 128;
    __shared__ double ss[256];
    __shared__ double ss2[256];
    int col = threadIdx.x & 127;
    int half = threadIdx.x >> 7;
    double s = 0.0, s2 = 0.0;
    for (int r = blockIdx.x * 2 + half; r < n; r += gridDim.x * 2) {
        float v = f[r * DFEAT + col];
        s += (double)v;
        s2 += (double)v * (double)v;
    }
    ss[threadIdx.x] = s;
    ss2[threadIdx.x] = s2;
    __syncthreads();
    if (half == 0) {
        atomicAdd(&sum[soff + col], ss[threadIdx.x] + ss[threadIdx.x + 128]);
        atomicAdd(&sumsq[soff + col], ss2[threadIdx.x] + ss2[threadIdx.x + 128]);
    }
}

__global__ void finalize_kernel(const double* __restrict__ sum, const double* __restrict__ sumsq,
                                float* __restrict__ mean, float* __restrict__ rstd, int n) {
    int i = threadIdx.x;
    if (i < 256) {
        double s = sum[i], s2 = sumsq[i];
        double m = s / (double)n;
        double var = (s2 - s * s / (double)n) / (double)(n - 1);
        double sd = sqrt(fmax(var, 0.0));
        sd = fmax(sd, 1e-12);
        mean[i] = (float)m;
        rstd[i] = (float)(1.0 / sd);
    }
}

__global__ void writeout2_kernel(const float* __restrict__ fA, const float* __restrict__ fB,
                                 const float* __restrict__ mean, const float* __restrict__ rstd,
                                 float* __restrict__ out, int n) {
    const float* f = blockIdx.y ? fB : fA;
    int soff4 = blockIdx.y * 32;
    float* o_base = out + (size_t)blockIdx.y * n * DFEAT;
    int idx = blockIdx.x * blockDim.x + threadIdx.x;  // over n*32 float4s
    if (idx >= n * 32) return;
    int c4 = idx & 31;
    float4 v = ((const float4*)f)[idx];
    float4 m = ((const float4*)mean)[soff4 + c4];
    float4 r = ((const float4*)rstd)[soff4 + c4];
    float4 o;
    o.x = (v.x - m.x) * r.x;
    o.y = (v.y - m.y) * r.y;
    o.z = (v.z - m.z) * r.z;
    o.w = (v.w - m.w) * r.w;
    ((float4*)o_base)[idx] = o;
}

// ---------------- host launcher ----------------

static void* sym_addr(const void* symbol) {
    void* p = nullptr;
    cudaGetSymbolAddress(&p, symbol);
    return p;
}

extern "C" void kernel_launch(void* const* d_in, const int* in_sizes, int n_in,
                              void* d_out, int out_size) {
    const float* feat1   = (const float*)d_in[0];
    const float* feat2   = (const float*)d_in[1];
    const int*   src1    = (const int*)d_in[2];
    const int*   dst1    = (const int*)d_in[3];
    const int*   src2    = (const int*)d_in[4];
    const int*   dst2    = (const int*)d_in[5];
    const float* weights = (const float*)d_in[6];
    const float* biases  = (const float*)d_in[7];
    const int E1 = in_sizes[2];
    const int E2 = in_sizes[4];
    const int N = NNODES;
    const int L = in_sizes[7] / DFEAT;

    float* p_a1    = (float*)sym_addr(g_bufA1);
    float* p_b1    = (float*)sym_addr(g_bufB1);
    float* p_a2    = (float*)sym_addr(g_bufA2);
    float* p_b2    = (float*)sym_addr(g_bufB2);
    float2* p_wp2  = (float2*)sym_addr(g_wp2);
    int*   p_col1  = (int*)sym_addr(g_col1);
    int*   p_col2  = (int*)sym_addr(g_col2);
    int*   p_deg1  = (int*)sym_addr(g_deg1);
    int*   p_deg2  = (int*)sym_addr(g_deg2);
    int*   p_rp1   = (int*)sym_addr(g_rowptr1);
    int*   p_rp2   = (int*)sym_addr(g_rowptr2);
    int*   p_cur1  = (int*)sym_addr(g_cursor1);
    int*   p_cur2  = (int*)sym_addr(g_cursor2);
    float* p_norm1 = (float*)sym_addr(g_norm1);
    float* p_norm2 = (float*)sym_addr(g_norm2);
    double* p_sum  = (double*)sym_addr(g_sum);
    double* p_sq   = (double*)sym_addr(g_sumsq);
    float* p_mean  = (float*)sym_addr(g_mean);
    float* p_rstd  = (float*)sym_addr(g_rstd);

    // allow 84KB dynamic smem for the fused kernel (idempotent)
    static bool attr_set = false;
    if (!attr_set) {
        cudaFuncSetAttribute(layer_fused_kernel,
                             cudaFuncAttributeMaxDynamicSharedMemorySize, SMEM_BYTES);
        attr_set = true;
    }

    // 1. zero deg + stats
    zero_kernel<<<(N + 255) / 256, 256>>>(p_deg1, p_deg2, p_sum, p_sq, N);

    // 2. degree histograms (both graphs)
    {
        int Emax = E1 > E2 ? E1 : E2;
        dim3 grid((Emax + 255) / 256, 2);
        hist2_kernel<<<grid, 256>>>(dst1, p_deg1, E1, dst2, p_deg2, E2);
    }

    // 3. scans (one block per graph)
    scan2_kernel<<<2, 1024>>>(p_deg1, p_rp1, p_cur1, p_norm1,
                              p_deg2, p_rp2, p_cur2, p_norm2, N);

    // 4. CSR fill (both graphs)
    {
        int Emax = E1 > E2 ? E1 : E2;
        dim3 grid((Emax + 255) / 256, 2);
        fill2_kernel<<<grid, 256>>>(src1, dst1, p_cur1, p_col1, E1,
                                    src2, dst2, p_cur2, p_col2, E2);
    }

    // 5. W' split+transposed per layer
    {
        dim3 grid((DFEAT * DFEAT + 255) / 256, L);
        wprime2_kernel<<<grid, 256>>>(weights, p_wp2);
    }

    // 6. GCNII layers: fused aggregate + GEMM (both graphs per launch).
    // Ping-pong buffers: layer input and output must be distinct (gather race).
    const dim3 layer_grid((N + 127) / 128, 2);
    const float* cur1 = feat1;
    const float* cur2 = feat2;
    float* out1 = p_a1;
    float* out2 = p_a2;
    for (int l = 0; l < L; l++) {
        const float2* Wl = p_wp2 + (size_t)l * DFEAT * DFEAT;
        const float* bl = biases + (size_t)l * DFEAT;
        layer_fused_kernel<<<layer_grid, 256, SMEM_BYTES>>>(
            cur1, feat1, p_norm1, p_rp1, p_col1, out1,
            cur2, feat2, p_norm2, p_rp2, p_col2, out2,
            Wl, bl, N);
        cur1 = out1;
        cur2 = out2;
        out1 = (out1 == p_a1) ? p_b1 : p_a1;
        out2 = (out2 == p_a2) ? p_b2 : p_a2;
    }
    const float* fin1 = cur1;
    const float* fin2 = cur2;

    // 7. column stats (both graphs)
    {
        dim3 grid(256, 2);
        colstats2_kernel<<<grid, 256>>>(fin1, fin2, p_sum, p_sq, N);
    }

    // 8. mean / rstd
    finalize_kernel<<<1, 256>>>(p_sum, p_sq, p_mean, p_rstd, N);

    // 9. standardized output: [h1 | h2]
    {
        dim3 grid((N * 32 + 255) / 256, 2);
        writeout2_kernel<<<grid, 256>>>(fin1, fin2, p_mean, p_rstd, (float*)d_out, N);
    }
}

// round 6
// speedup vs baseline: 1.3837x; 1.3837x over previous
#include <cuda_runtime.h>
#include <cuda_bf16.h>
#include <math.h>
#include <stdint.h>

// Problem constants (fixed by reference)
#define NNODES 100000
#define DFEAT  128
#define EMAX   1600000
#define ALPHA_C 0.1f
#define LMAX   8

// ---------------- scratch (device globals; no allocation allowed) ----------------
__device__ float  g_h1[NNODES * DFEAT];
__device__ float  g_h2[NNODES * DFEAT];
__device__ float  g_f1[NNODES * DFEAT];
__device__ float  g_f2[NNODES * DFEAT];
__device__ float2 g_wp2[LMAX * DFEAT * DFEAT];   // [l][n][k] = (hi, lo) of W'[k][n]
__device__ int    g_col1[EMAX];
__device__ int    g_col2[EMAX];
__device__ int    g_deg1[NNODES];
__device__ int    g_deg2[NNODES];
__device__ int    g_rowptr1[NNODES + 1];
__device__ int    g_rowptr2[NNODES + 1];
__device__ int    g_cursor1[NNODES];
__device__ int    g_cursor2[NNODES];
__device__ float  g_norm1[NNODES];
__device__ float  g_norm2[NNODES];
__device__ double g_sum[256];    // [graph*128 + col]
__device__ double g_sumsq[256];
__device__ float  g_mean[256];
__device__ float  g_rstd[256];

// ---------------- setup kernels ----------------

// zero both degree arrays + stats accumulators (pre-fork)
__global__ void zero_kernel(int* d1, int* d2, double* s, double* s2, int n) {
    int i = blockIdx.x * blockDim.x + threadIdx.x;
    if (i < n) { d1[i] = 0; d2[i] = 0; }
    if (i < 256) { s[i] = 0.0; s2[i] = 0.0; }
}

__global__ void hist_kernel(const int* __restrict__ dst, int* __restrict__ deg, int E) {
    int i = blockIdx.x * blockDim.x + threadIdx.x;
    if (i < E) atomicAdd(&deg[dst[i]], 1);
}

// single-block scan: 1024 threads, 4 elems/thread, warp-shuffle scan.
__global__ __launch_bounds__(1024) void scan_kernel(
    const int* __restrict__ deg, int* __restrict__ rp, int* __restrict__ cur,
    float* __restrict__ norm, int n)
{
    __shared__ int wsum[32];
    __shared__ int s_carry;
    int tid = threadIdx.x, lane = tid & 31, wid = tid >> 5;
    if (tid == 0) s_carry = 0;
    __syncthreads();

    for (int base = 0; base < n; base += 4096) {
        int idx = base + tid * 4;
        int v0 = (idx + 0 < n) ? deg[idx + 0] : 0;
        int v1 = (idx + 1 < n) ? deg[idx + 1] : 0;
        int v2 = (idx + 2 < n) ? deg[idx + 2] : 0;
        int v3 = (idx + 3 < n) ? deg[idx + 3] : 0;
        int p0 = v0, p1 = p0 + v1, p2 = p1 + v2, p3 = p2 + v3;
        int tot = p3;
        #pragma unroll
        for (int off = 1; off < 32; off <<= 1) {
            int t = __shfl_up_sync(0xFFFFFFFFu, tot, off);
            if (lane >= off) tot += t;
        }
        if (lane == 31) wsum[wid] = tot;
        __syncthreads();
        if (wid == 0) {
            int w = wsum[lane];
            #pragma unroll
            for (int off = 1; off < 32; off <<= 1) {
                int t = __shfl_up_sync(0xFFFFFFFFu, w, off);
                if (lane >= off) w += t;
            }
            wsum[lane] = w;
        }
        __syncthreads();
        int carry = s_carry;
        int excl = carry + (wid ? wsum[wid - 1] : 0) + (tot - p3);
        if (idx + 0 < n) { rp[idx + 0] = excl;      cur[idx + 0] = excl;      norm[idx + 0] = rsqrtf(fmaxf((float)v0, 1.f)); }
        if (idx + 1 < n) { rp[idx + 1] = excl + p0; cur[idx + 1] = excl + p0; norm[idx + 1] = rsqrtf(fmaxf((float)v1, 1.f)); }
        if (idx + 2 < n) { rp[idx + 2] = excl + p1; cur[idx + 2] = excl + p1; norm[idx + 2] = rsqrtf(fmaxf((float)v2, 1.f)); }
        if (idx + 3 < n) { rp[idx + 3] = excl + p2; cur[idx + 3] = excl + p2; norm[idx + 3] = rsqrtf(fmaxf((float)v3, 1.f)); }
        __syncthreads();
        if (tid == 0) s_carry = carry + wsum[31];
        __syncthreads();
    }
    if (tid == 0) rp[n] = s_carry;
}

__global__ void fill_kernel(const int* __restrict__ src, const int* __restrict__ dst,
                            int* __restrict__ cursor, int* __restrict__ col, int E) {
    int i = blockIdx.x * blockDim.x + threadIdx.x;
    if (i < E) {
        int d = dst[i];
        int p = atomicAdd(&cursor[d], 1);
        col[p] = src[i];
    }
}

// W' = (1-beta)*I + beta*W, split into tf32 hi/lo, stored transposed [n][k]
__global__ void wprime2_kernel(const float* __restrict__ W, float2* __restrict__ Wp2) {
    int l = blockIdx.y;
    int i = blockIdx.x * blockDim.x + threadIdx.x;   // 0..16383
    if (i >= DFEAT * DFEAT) return;
    float beta = logf(1.0f / (float)(l + 1) + 1.0f); // LAMBDA = 1
    int n = i >> 7, k = i & 127;
    float v = beta * W[l * DFEAT * DFEAT + k * DFEAT + n];
    if (k == n) v += 1.0f - beta;
    float hi = __uint_as_float(__float_as_uint(v) & 0xFFFFE000u);
    float lo = v - hi;
    Wp2[l * DFEAT * DFEAT + i] = make_float2(hi, lo);
}

// ---------------- aggregate (warp-per-row, single graph) ----------------
// h[i] = (1-ALPHA)*norm[i]*sum_{e in row i} norm[src]*feat[src] + ALPHA*feat0[i]
__global__ __launch_bounds__(256) void aggregate_kernel(
    const float* __restrict__ feat, const float* __restrict__ feat0,
    const float* __restrict__ norm, const int* __restrict__ rowptr,
    const int* __restrict__ col, float* __restrict__ h, int n)
{
    int warp = (blockIdx.x * blockDim.x + threadIdx.x) >> 5;
    int lane = threadIdx.x & 31;
    if (warp >= n) return;
    int e0 = __ldg(&rowptr[warp]);
    int e1 = __ldg(&rowptr[warp + 1]);
    float4 acc = make_float4(0.f, 0.f, 0.f, 0.f);
    int e = e0;
    for (; e + 3 < e1; e += 4) {
        int s0 = __ldg(&col[e]);
        int s1 = __ldg(&col[e + 1]);
        int s2 = __ldg(&col[e + 2]);
        int s3 = __ldg(&col[e + 3]);
        float n0 = __ldg(&norm[s0]);
        float n1 = __ldg(&norm[s1]);
        float n2 = __ldg(&norm[s2]);
        float n3 = __ldg(&norm[s3]);
        float4 v0 = __ldg((const float4*)&feat[s0 * DFEAT + lane * 4]);
        float4 v1 = __ldg((const float4*)&feat[s1 * DFEAT + lane * 4]);
        float4 v2 = __ldg((const float4*)&feat[s2 * DFEAT + lane * 4]);
        float4 v3 = __ldg((const float4*)&feat[s3 * DFEAT + lane * 4]);
        acc.x += n0 * v0.x + n1 * v1.x + n2 * v2.x + n3 * v3.x;
        acc.y += n0 * v0.y + n1 * v1.y + n2 * v2.y + n3 * v3.y;
        acc.z += n0 * v0.z + n1 * v1.z + n2 * v2.z + n3 * v3.z;
        acc.w += n0 * v0.w + n1 * v1.w + n2 * v2.w + n3 * v3.w;
    }
    for (; e < e1; e++) {
        int s0 = __ldg(&col[e]);
        float n0 = __ldg(&norm[s0]);
        float4 v0 = __ldg((const float4*)&feat[s0 * DFEAT + lane * 4]);
        acc.x += n0 * v0.x; acc.y += n0 * v0.y;
        acc.z += n0 * v0.z; acc.w += n0 * v0.w;
    }
    float scale = (1.0f - ALPHA_C) * __ldg(&norm[warp]);
    float4 f0v = __ldg((const float4*)&feat0[warp * DFEAT + lane * 4]);
    float4 o;
    o.x = scale * acc.x + ALPHA_C * f0v.x;
    o.y = scale * acc.y + ALPHA_C * f0v.y;
    o.z = scale * acc.z + ALPHA_C * f0v.z;
    o.w = scale * acc.w + ALPHA_C * f0v.w;
    *(float4*)&h[warp * DFEAT + lane * 4] = o;
}

// ---------------- 3xTF32 tensor-core GEMM (single graph) ----------------
// feat_out = relu(h @ W' + bias) via mma.sync m16n8k8 tf32 with hi/lo split.
// Block tile 128x128, BK=16, 8 warps, warp tile 64x32.

__device__ __forceinline__ void mma_tf32(float c[4], const uint32_t a[4],
                                         uint32_t b0, uint32_t b1) {
    asm volatile(
        "mma.sync.aligned.m16n8k8.row.col.f32.tf32.tf32.f32 "
        "{%0,%1,%2,%3}, {%4,%5,%6,%7}, {%8,%9}, {%0,%1,%2,%3};\n"
        : "+f"(c[0]), "+f"(c[1]), "+f"(c[2]), "+f"(c[3])
        : "r"(a[0]), "r"(a[1]), "r"(a[2]), "r"(a[3]), "r"(b0), "r"(b1));
}

#define HS_STRIDE 18   // float2 stride per row (16 + 2 pad)

__global__ __launch_bounds__(256, 2) void gemm_tc_kernel(
    const float* __restrict__ h, float* __restrict__ out,
    const float2* __restrict__ Wp2, const float* __restrict__ bias, int nrows)
{
    __shared__ float2 Hs[128 * HS_STRIDE];  // [row][k] (hi,lo)
    __shared__ float2 Ws[128 * HS_STRIDE];  // [n][k]   (hi,lo)

    const int tid = threadIdx.x;
    const int wid = tid >> 5;
    const int lane = tid & 31;
    const int g = lane >> 2;      // 0..7
    const int tg = lane & 3;      // 0..3
    const int warpM = wid & 1;    // 2 over M: 64 rows each
    const int warpN = wid >> 1;   // 4 over N: 32 cols each
    const int M0w = warpM * 64;
    const int N0w = warpN * 32;
    const int blockRow = blockIdx.x * 128;

    float c[4][4][4];   // [mt][nt][frag]
    #pragma unroll
    for (int mt = 0; mt < 4; mt++)
        #pragma unroll
        for (int nt = 0; nt < 4; nt++)
            #pragma unroll
            for (int q = 0; q < 4; q++) c[mt][nt][q] = 0.f;

    for (int stage = 0; stage < 8; stage++) {
        const int ks0 = stage * 16;
        // fill Hs: 128 rows x 16 k (512 float4 of h), split hi/lo
        #pragma unroll
        for (int it = 0; it < 2; it++) {
            int f = tid + it * 256;          // 0..511
            int row = f >> 2;
            int kq = f & 3;
            int grow = blockRow + row;
            float4 v = make_float4(0.f, 0.f, 0.f, 0.f);
            if (grow < nrows)
                v = *(const float4*)&h[grow * DFEAT + ks0 + kq * 4];
            float2* dst = &Hs[row * HS_STRIDE + kq * 4];
            float hx = __uint_as_float(__float_as_uint(v.x) & 0xFFFFE000u);
            float hy = __uint_as_float(__float_as_uint(v.y) & 0xFFFFE000u);
            float hz = __uint_as_float(__float_as_uint(v.z) & 0xFFFFE000u);
            float hw = __uint_as_float(__float_as_uint(v.w) & 0xFFFFE000u);
            ((float4*)dst)[0] = make_float4(hx, v.x - hx, hy, v.y - hy);
            ((float4*)dst)[1] = make_float4(hz, v.z - hz, hw, v.w - hw);
        }
        // fill Ws: copy pre-split Wp2 [n][k]: 1024 float4
        #pragma unroll
        for (int it = 0; it < 4; it++) {
            int f = tid + it * 256;          // 0..1023
            int n = f >> 3;
            int q = f & 7;                   // 8 float4 per n-row
            float4 v = *(const float4*)&Wp2[n * DFEAT + ks0 + q * 2];
            *(float4*)&Ws[n * HS_STRIDE + q * 2] = v;
        }
        __syncthreads();

        #pragma unroll
        for (int ks = 0; ks < 2; ks++) {
            const int K0 = ks * 8;
            uint32_t ah[4][4], al[4][4];
            #pragma unroll
            for (int mt = 0; mt < 4; mt++) {
                int base = (M0w + mt * 16 + g) * HS_STRIDE + K0 + tg;
                float2 v0 = Hs[base];
                float2 v1 = Hs[base + 8 * HS_STRIDE];
                float2 v2 = Hs[base + 4];
                float2 v3 = Hs[base + 8 * HS_STRIDE + 4];
                ah[mt][0] = __float_as_uint(v0.x); al[mt][0] = __float_as_uint(v0.y);
                ah[mt][1] = __float_as_uint(v1.x); al[mt][1] = __float_as_uint(v1.y);
                ah[mt][2] = __float_as_uint(v2.x); al[mt][2] = __float_as_uint(v2.y);
                ah[mt][3] = __float_as_uint(v3.x); al[mt][3] = __float_as_uint(v3.y);
            }
            uint32_t bh[4][2], bl[4][2];
            #pragma unroll
            for (int nt = 0; nt < 4; nt++) {
                int base = (N0w + nt * 8 + g) * HS_STRIDE + K0 + tg;
                float2 v0 = Ws[base];
                float2 v1 = Ws[base + 4];
                bh[nt][0] = __float_as_uint(v0.x); bl[nt][0] = __float_as_uint(v0.y);
                bh[nt][1] = __float_as_uint(v1.x); bl[nt][1] = __float_as_uint(v1.y);
            }
            #pragma unroll
            for (int mt = 0; mt < 4; mt++)
                #pragma unroll
                for (int nt = 0; nt < 4; nt++) {
                    mma_tf32(c[mt][nt], ah[mt], bh[nt][0], bh[nt][1]);
                    mma_tf32(c[mt][nt], ah[mt], bl[nt][0], bl[nt][1]);
                    mma_tf32(c[mt][nt], al[mt], bh[nt][0], bh[nt][1]);
                }
        }
        __syncthreads();
    }

    // epilogue: relu(c + bias)
    #pragma unroll
    for (int mt = 0; mt < 4; mt++) {
        int row0 = blockRow + M0w + mt * 16 + g;
        int row1 = row0 + 8;
        #pragma unroll
        for (int nt = 0; nt < 4; nt++) {
            int colj = N0w + nt * 8 + 2 * tg;
            float2 bv = *(const float2*)&bias[colj];
            if (row0 < nrows) {
                float2 o0;
                o0.x = fmaxf(c[mt][nt][0] + bv.x, 0.f);
                o0.y = fmaxf(c[mt][nt][1] + bv.y, 0.f);
                *(float2*)&out[row0 * DFEAT + colj] = o0;
            }
            if (row1 < nrows) {
                float2 o1;
                o1.x = fmaxf(c[mt][nt][2] + bv.x, 0.f);
                o1.y = fmaxf(c[mt][nt][3] + bv.y, 0.f);
                *(float2*)&out[row1 * DFEAT + colj] = o1;
            }
        }
    }
}

// ---------------- stats / output kernels ----------------

__global__ void colstats_kernel(const float* __restrict__ f, double* __restrict__ sum,
                                double* __restrict__ sumsq, int n) {
    __shared__ double ss[256];
    __shared__ double ss2[256];
    int col = threadIdx.x & 127;
    int half = threadIdx.x >> 7;
    double s = 0.0, s2 = 0.0;
    for (int r = blockIdx.x * 2 + half; r < n; r += gridDim.x * 2) {
        float v = f[r * DFEAT + col];
        s += (double)v;
        s2 += (double)v * (double)v;
    }
    ss[threadIdx.x] = s;
    ss2[threadIdx.x] = s2;
    __syncthreads();
    if (half == 0) {
        atomicAdd(&sum[col], ss[threadIdx.x] + ss[threadIdx.x + 128]);
        atomicAdd(&sumsq[col], ss2[threadIdx.x] + ss2[threadIdx.x + 128]);
    }
}

__global__ void finalize_kernel(const double* __restrict__ sum, const double* __restrict__ sumsq,
                                float* __restrict__ mean, float* __restrict__ rstd, int n) {
    int i = threadIdx.x;
    if (i < 256) {
        double s = sum[i], s2 = sumsq[i];
        double m = s / (double)n;
        double var = (s2 - s * s / (double)n) / (double)(n - 1);
        double sd = sqrt(fmax(var, 0.0));
        sd = fmax(sd, 1e-12);
        mean[i] = (float)m;
        rstd[i] = (float)(1.0 / sd);
    }
}

__global__ void writeout2_kernel(const float* __restrict__ fA, const float* __restrict__ fB,
                                 const float* __restrict__ mean, const float* __restrict__ rstd,
                                 float* __restrict__ out, int n) {
    const float* f = blockIdx.y ? fB : fA;
    int soff4 = blockIdx.y * 32;
    float* o_base = out + (size_t)blockIdx.y * n * DFEAT;
    int idx = blockIdx.x * blockDim.x + threadIdx.x;  // over n*32 float4s
    if (idx >= n * 32) return;
    int c4 = idx & 31;
    float4 v = ((const float4*)f)[idx];
    float4 m = ((const float4*)mean)[soff4 + c4];
    float4 r = ((const float4*)rstd)[soff4 + c4];
    float4 o;
    o.x = (v.x - m.x) * r.x;
    o.y = (v.y - m.y) * r.y;
    o.z = (v.z - m.z) * r.z;
    o.w = (v.w - m.w) * r.w;
    ((float4*)o_base)[idx] = o;
}

// ---------------- host launcher ----------------

static void* sym_addr(const void* symbol) {
    void* p = nullptr;
    cudaGetSymbolAddress(&p, symbol);
    return p;
}

extern "C" void kernel_launch(void* const* d_in, const int* in_sizes, int n_in,
                              void* d_out, int out_size) {
    const float* feat1   = (const float*)d_in[0];
    const float* feat2   = (const float*)d_in[1];
    const int*   src1    = (const int*)d_in[2];
    const int*   dst1    = (const int*)d_in[3];
    const int*   src2    = (const int*)d_in[4];
    const int*   dst2    = (const int*)d_in[5];
    const float* weights = (const float*)d_in[6];
    const float* biases  = (const float*)d_in[7];
    const int E1 = in_sizes[2];
    const int E2 = in_sizes[4];
    const int N = NNODES;
    const int L = in_sizes[7] / DFEAT;

    float* p_h1    = (float*)sym_addr(g_h1);
    float* p_h2    = (float*)sym_addr(g_h2);
    float* p_f1    = (float*)sym_addr(g_f1);
    float* p_f2    = (float*)sym_addr(g_f2);
    float2* p_wp2  = (float2*)sym_addr(g_wp2);
    int*   p_col1  = (int*)sym_addr(g_col1);
    int*   p_col2  = (int*)sym_addr(g_col2);
    int*   p_deg1  = (int*)sym_addr(g_deg1);
    int*   p_deg2  = (int*)sym_addr(g_deg2);
    int*   p_rp1   = (int*)sym_addr(g_rowptr1);
    int*   p_rp2   = (int*)sym_addr(g_rowptr2);
    int*   p_cur1  = (int*)sym_addr(g_cursor1);
    int*   p_cur2  = (int*)sym_addr(g_cursor2);
    float* p_norm1 = (float*)sym_addr(g_norm1);
    float* p_norm2 = (float*)sym_addr(g_norm2);
    double* p_sum  = (double*)sym_addr(g_sum);
    double* p_sq   = (double*)sym_addr(g_sumsq);
    float* p_mean  = (float*)sym_addr(g_mean);
    float* p_rstd  = (float*)sym_addr(g_rstd);

    // one-time: second stream + fork/join events (created outside graph capture
    // on the correctness run; only record/wait are issued during capture)
    static cudaStream_t s2 = nullptr;
    static cudaEvent_t evFork = nullptr, evJoin = nullptr;
    if (s2 == nullptr) {
        cudaStreamCreateWithFlags(&s2, cudaStreamNonBlocking);
        cudaEventCreateWithFlags(&evFork, cudaEventDisableTiming);
        cudaEventCreateWithFlags(&evJoin, cudaEventDisableTiming);
    }
    cudaStream_t s0 = 0;  // legacy default stream (what the harness captures)

    // ---- pre-fork (s0): zero + W' ----
    zero_kernel<<<(N + 255) / 256, 256, 0, s0>>>(p_deg1, p_deg2, p_sum, p_sq, N);
    {
        dim3 grid((DFEAT * DFEAT + 255) / 256, L);
        wprime2_kernel<<<grid, 256, 0, s0>>>(weights, p_wp2);
    }

    // ---- fork: s2 depends on pre-fork work ----
    cudaEventRecord(evFork, s0);
    cudaStreamWaitEvent(s2, evFork, 0);

    const int agg_blocks = (N * 32 + 255) / 256;
    const int gemm_blocks = (N + 127) / 128;

    // ---- chain for graph 1 on s0 ----
    hist_kernel<<<(E1 + 255) / 256, 256, 0, s0>>>(dst1, p_deg1, E1);
    scan_kernel<<<1, 1024, 0, s0>>>(p_deg1, p_rp1, p_cur1, p_norm1, N);
    fill_kernel<<<(E1 + 255) / 256, 256, 0, s0>>>(src1, dst1, p_cur1, p_col1, E1);
    {
        const float* cur = feat1;
        for (int l = 0; l < L; l++) {
            const float2* Wl = p_wp2 + (size_t)l * DFEAT * DFEAT;
            const float* bl = biases + (size_t)l * DFEAT;
            aggregate_kernel<<<agg_blocks, 256, 0, s0>>>(cur, feat1, p_norm1, p_rp1, p_col1, p_h1, N);
            gemm_tc_kernel<<<gemm_blocks, 256, 0, s0>>>(p_h1, p_f1, Wl, bl, N);
            cur = p_f1;
        }
    }
    colstats_kernel<<<256, 256, 0, s0>>>(p_f1, p_sum, p_sq, N);

    // ---- chain for graph 2 on s2 ----
    hist_kernel<<<(E2 + 255) / 256, 256, 0, s2>>>(dst2, p_deg2, E2);
    scan_kernel<<<1, 1024, 0, s2>>>(p_deg2, p_rp2, p_cur2, p_norm2, N);
    fill_kernel<<<(E2 + 255) / 256, 256, 0, s2>>>(src2, dst2, p_cur2, p_col2, E2);
    {
        const float* cur = feat2;
        for (int l = 0; l < L; l++) {
            const float2* Wl = p_wp2 + (size_t)l * DFEAT * DFEAT;
            const float* bl = biases + (size_t)l * DFEAT;
            aggregate_kernel<<<agg_blocks, 256, 0, s2>>>(cur, feat2, p_norm2, p_rp2, p_col2, p_h2, N);
            gemm_tc_kernel<<<gemm_blocks, 256, 0, s2>>>(p_h2, p_f2, Wl, bl, N);
            cur = p_f2;
        }
    }
    colstats_kernel<<<256, 256, 0, s2>>>(p_f2, p_sum + 128, p_sq + 128, N);

    // ---- join: s0 waits for graph-2 chain ----
    cudaEventRecord(evJoin, s2);
    cudaStreamWaitEvent(s0, evJoin, 0);

    // ---- finalize + writeout (s0) ----
    finalize_kernel<<<1, 256, 0, s0>>>(p_sum, p_sq, p_mean, p_rstd, N);
    {
        dim3 grid((N * 32 + 255) / 256, 2);
        writeout2_kernel<<<grid, 256, 0, s0>>>(p_f1, p_f2, p_mean, p_rstd, (float*)d_out, N);
    }
}

// round 7
// speedup vs baseline: 1.5645x; 1.1307x over previous
#include <cuda_runtime.h>
#include <cuda_fp16.h>
#include <math.h>
#include <stdint.h>

// Problem constants (fixed by reference)
#define NNODES 100000
#define DFEAT  128
#define EMAX   1600000
#define ALPHA_C 0.1f
#define LMAX   8
#define SCAN_BLOCKS ((NNODES + 1023) / 1024)   // 98

// ---------------- scratch (device globals; no allocation allowed) ----------------
__device__ float  g_h1[NNODES * DFEAT];
__device__ float  g_h2[NNODES * DFEAT];
__device__ float  g_f1[NNODES * DFEAT];
__device__ float  g_f2[NNODES * DFEAT];
__device__ __half g_hf1[NNODES * DFEAT];   // fp16 gather operand (input copy, then layer outputs)
__device__ __half g_hf2[NNODES * DFEAT];
__device__ float2 g_wp2[LMAX * DFEAT * DFEAT];   // [l][n][k] = (hi, lo) of W'[k][n]
__device__ int    g_col1[EMAX];
__device__ int    g_col2[EMAX];
__device__ int    g_deg1[NNODES];
__device__ int    g_deg2[NNODES];
__device__ int    g_psum1[SCAN_BLOCKS];
__device__ int    g_psum2[SCAN_BLOCKS];
__device__ int    g_rowptr1[NNODES + 1];
__device__ int    g_rowptr2[NNODES + 1];
__device__ int    g_cursor1[NNODES];
__device__ int    g_cursor2[NNODES];
__device__ float  g_norm1[NNODES];
__device__ float  g_norm2[NNODES];
__device__ double g_sum[256];    // [graph*128 + col]
__device__ double g_sumsq[256];
__device__ float  g_mean[256];
__device__ float  g_rstd[256];

// ---------------- setup kernels ----------------

__global__ void zero_kernel(int* d1, int* d2, double* s, double* s2, int n) {
    int i = blockIdx.x * blockDim.x + threadIdx.x;
    if (i < n) { d1[i] = 0; d2[i] = 0; }
    if (i < 256) { s[i] = 0.0; s2[i] = 0.0; }
}

__global__ void hist_kernel(const int* __restrict__ dst, int* __restrict__ deg, int E) {
    int i = blockIdx.x * blockDim.x + threadIdx.x;
    if (i < E) atomicAdd(&deg[dst[i]], 1);
}

// phase 1: per-block (1024 elems) sums
__global__ __launch_bounds__(256) void scan_partial_kernel(const int* __restrict__ deg,
                                                           int* __restrict__ psum, int n) {
    int b = blockIdx.x, t = threadIdx.x;
    int idx = b * 1024 + t * 4;
    int s = 0;
    #pragma unroll
    for (int i = 0; i < 4; i++)
        if (idx + i < n) s += deg[idx + i];
    #pragma unroll
    for (int o = 16; o; o >>= 1) s += __shfl_down_sync(0xFFFFFFFFu, s, o);
    __shared__ int ws[8];
    if ((t & 31) == 0) ws[t >> 5] = s;
    __syncthreads();
    if (t == 0) {
        int v = 0;
        #pragma unroll
        for (int i = 0; i < 8; i++) v += ws[i];
        psum[b] = v;
    }
}

// phase 2: per-block local scan + fold prefix of psum; writes rowptr/cursor/norm
__global__ __launch_bounds__(256) void scan_apply_kernel(
    const int* __restrict__ deg, const int* __restrict__ psum,
    int* __restrict__ rp, int* __restrict__ cur, float* __restrict__ norm, int n)
{
    int b = blockIdx.x, t = threadIdx.x, lane = t & 31, wid = t >> 5;
    __shared__ int sh[16];
    __shared__ int s_off;

    // block offset = sum psum[0..b)   (b <= 97 < 256: each thread loads <=1)
    int off = (t < b) ? psum[t] : 0;
    #pragma unroll
    for (int o = 16; o; o >>= 1) off += __shfl_down_sync(0xFFFFFFFFu, off, o);
    if (lane == 0) sh[wid] = off;
    __syncthreads();
    if (t == 0) {
        int v = 0;
        #pragma unroll
        for (int i = 0; i < 8; i++) v += sh[i];
        s_off = v;
    }
    __syncthreads();
    off = s_off;

    // local scan of 1024 elems
    int idx = b * 1024 + t * 4;
    int v0 = (idx + 0 < n) ? deg[idx + 0] : 0;
    int v1 = (idx + 1 < n) ? deg[idx + 1] : 0;
    int v2 = (idx + 2 < n) ? deg[idx + 2] : 0;
    int v3 = (idx + 3 < n) ? deg[idx + 3] : 0;
    int p0 = v0, p1 = p0 + v1, p2 = p1 + v2, p3 = p2 + v3;
    int tot = p3;
    #pragma unroll
    for (int o = 1; o < 32; o <<= 1) {
        int x = __shfl_up_sync(0xFFFFFFFFu, tot, o);
        if (lane >= o) tot += x;
    }
    if (lane == 31) sh[wid] = tot;
    __syncthreads();
    if (wid == 0 && lane < 8) {
        int w = sh[lane];
        #pragma unroll
        for (int o = 1; o < 8; o <<= 1) {
            int x = __shfl_up_sync(0xFFu, w, o);
            if (lane >= o) w += x;
        }
        sh[8 + lane] = w;   // inclusive warp prefix
    }
    __syncthreads();
    int excl = off + (wid ? sh[8 + wid - 1] : 0) + (tot - p3);
    if (idx + 0 < n) { rp[idx + 0] = excl;      cur[idx + 0] = excl;      norm[idx + 0] = rsqrtf(fmaxf((float)v0, 1.f)); }
    if (idx + 1 < n) { rp[idx + 1] = excl + p0; cur[idx + 1] = excl + p0; norm[idx + 1] = rsqrtf(fmaxf((float)v1, 1.f)); }
    if (idx + 2 < n) { rp[idx + 2] = excl + p1; cur[idx + 2] = excl + p1; norm[idx + 2] = rsqrtf(fmaxf((float)v2, 1.f)); }
    if (idx + 3 < n) { rp[idx + 3] = excl + p2; cur[idx + 3] = excl + p2; norm[idx + 3] = rsqrtf(fmaxf((float)v3, 1.f)); }
    if (b == gridDim.x - 1 && t == 255) rp[n] = off + sh[8 + 7];
}

__global__ void fill_kernel(const int* __restrict__ src, const int* __restrict__ dst,
                            int* __restrict__ cursor, int* __restrict__ col, int E) {
    int i = blockIdx.x * blockDim.x + threadIdx.x;
    if (i < E) {
        int d = dst[i];
        int p = atomicAdd(&cursor[d], 1);
        col[p] = src[i];
    }
}

// fp32 -> fp16 copy (4 elems per thread)
__global__ void tohalf_kernel(const float* __restrict__ f, __half* __restrict__ o, int n4) {
    int i = blockIdx.x * blockDim.x + threadIdx.x;
    if (i >= n4) return;
    float4 v = ((const float4*)f)[i];
    __half2 a = __floats2half2_rn(v.x, v.y);
    __half2 b = __floats2half2_rn(v.z, v.w);
    ((uint2*)o)[i] = make_uint2(*(uint32_t*)&a, *(uint32_t*)&b);
}

// W' = (1-beta)*I + beta*W, split into tf32 hi/lo, stored transposed [n][k]
__global__ void wprime2_kernel(const float* __restrict__ W, float2* __restrict__ Wp2) {
    int l = blockIdx.y;
    int i = blockIdx.x * blockDim.x + threadIdx.x;   // 0..16383
    if (i >= DFEAT * DFEAT) return;
    float beta = logf(1.0f / (float)(l + 1) + 1.0f); // LAMBDA = 1
    int n = i >> 7, k = i & 127;
    float v = beta * W[l * DFEAT * DFEAT + k * DFEAT + n];
    if (k == n) v += 1.0f - beta;
    float hi = __uint_as_float(__float_as_uint(v) & 0xFFFFE000u);
    float lo = v - hi;
    Wp2[l * DFEAT * DFEAT + i] = make_float2(hi, lo);
}

// ---------------- aggregate (warp-per-row, fp16 gather operand) ----------------
// h[i] = (1-ALPHA)*norm[i]*sum_{e in row i} norm[src]*feat16[src] + ALPHA*feat0_fp32[i]
__global__ __launch_bounds__(256) void aggregate_h_kernel(
    const __half* __restrict__ feat16, const float* __restrict__ feat0,
    const float* __restrict__ norm, const int* __restrict__ rowptr,
    const int* __restrict__ col, float* __restrict__ h, int n)
{
    int warp = (blockIdx.x * blockDim.x + threadIdx.x) >> 5;
    int lane = threadIdx.x & 31;
    if (warp >= n) return;
    int e0 = __ldg(&rowptr[warp]);
    int e1 = __ldg(&rowptr[warp + 1]);
    float4 acc = make_float4(0.f, 0.f, 0.f, 0.f);
    int e = e0;
    for (; e + 3 < e1; e += 4) {
        int s0 = __ldg(&col[e]);
        int s1 = __ldg(&col[e + 1]);
        int s2 = __ldg(&col[e + 2]);
        int s3 = __ldg(&col[e + 3]);
        float n0 = __ldg(&norm[s0]);
        float n1 = __ldg(&norm[s1]);
        float n2 = __ldg(&norm[s2]);
        float n3 = __ldg(&norm[s3]);
        uint2 d0 = __ldg((const uint2*)&feat16[s0 * DFEAT + lane * 4]);
        uint2 d1 = __ldg((const uint2*)&feat16[s1 * DFEAT + lane * 4]);
        uint2 d2 = __ldg((const uint2*)&feat16[s2 * DFEAT + lane * 4]);
        uint2 d3 = __ldg((const uint2*)&feat16[s3 * DFEAT + lane * 4]);
        float2 a0 = __half22float2(*(__half2*)&d0.x), b0 = __half22float2(*(__half2*)&d0.y);
        float2 a1 = __half22float2(*(__half2*)&d1.x), b1 = __half22float2(*(__half2*)&d1.y);
        float2 a2 = __half22float2(*(__half2*)&d2.x), b2 = __half22float2(*(__half2*)&d2.y);
        float2 a3 = __half22float2(*(__half2*)&d3.x), b3 = __half22float2(*(__half2*)&d3.y);
        acc.x += n0 * a0.x + n1 * a1.x + n2 * a2.x + n3 * a3.x;
        acc.y += n0 * a0.y + n1 * a1.y + n2 * a2.y + n3 * a3.y;
        acc.z += n0 * b0.x + n1 * b1.x + n2 * b2.x + n3 * b3.x;
        acc.w += n0 * b0.y + n1 * b1.y + n2 * b2.y + n3 * b3.y;
    }
    for (; e < e1; e++) {
        int s0 = __ldg(&col[e]);
        float n0 = __ldg(&norm[s0]);
        uint2 d0 = __ldg((const uint2*)&feat16[s0 * DFEAT + lane * 4]);
        float2 a0 = __half22float2(*(__half2*)&d0.x), b0 = __half22float2(*(__half2*)&d0.y);
        acc.x += n0 * a0.x; acc.y += n0 * a0.y;
        acc.z += n0 * b0.x; acc.w += n0 * b0.y;
    }
    float scale = (1.0f - ALPHA_C) * __ldg(&norm[warp]);
    float4 f0v = __ldg((const float4*)&feat0[warp * DFEAT + lane * 4]);
    float4 o;
    o.x = scale * acc.x + ALPHA_C * f0v.x;
    o.y = scale * acc.y + ALPHA_C * f0v.y;
    o.z = scale * acc.z + ALPHA_C * f0v.z;
    o.w = scale * acc.w + ALPHA_C * f0v.w;
    *(float4*)&h[warp * DFEAT + lane * 4] = o;
}

// ---------------- 3xTF32 tensor-core GEMM ----------------
// out = relu(h @ W' + bias); writes fp16 (intermediate layers) and/or fp32 (final).

__device__ __forceinline__ void mma_tf32(float c[4], const uint32_t a[4],
                                         uint32_t b0, uint32_t b1) {
    asm volatile(
        "mma.sync.aligned.m16n8k8.row.col.f32.tf32.tf32.f32 "
        "{%0,%1,%2,%3}, {%4,%5,%6,%7}, {%8,%9}, {%0,%1,%2,%3};\n"
        : "+f"(c[0]), "+f"(c[1]), "+f"(c[2]), "+f"(c[3])
        : "r"(a[0]), "r"(a[1]), "r"(a[2]), "r"(a[3]), "r"(b0), "r"(b1));
}

#define HS_STRIDE 18   // float2 stride per row (16 + 2 pad)

__global__ __launch_bounds__(256, 2) void gemm_tc_kernel(
    const float* __restrict__ h, __half* __restrict__ out16, float* __restrict__ out32,
    const float2* __restrict__ Wp2, const float* __restrict__ bias, int nrows)
{
    __shared__ float2 Hs[128 * HS_STRIDE];  // [row][k] (hi,lo)
    __shared__ float2 Ws[128 * HS_STRIDE];  // [n][k]   (hi,lo)

    const int tid = threadIdx.x;
    const int wid = tid >> 5;
    const int lane = tid & 31;
    const int g = lane >> 2;      // 0..7
    const int tg = lane & 3;      // 0..3
    const int warpM = wid & 1;    // 2 over M: 64 rows each
    const int warpN = wid >> 1;   // 4 over N: 32 cols each
    const int M0w = warpM * 64;
    const int N0w = warpN * 32;
    const int blockRow = blockIdx.x * 128;

    float c[4][4][4];   // [mt][nt][frag]
    #pragma unroll
    for (int mt = 0; mt < 4; mt++)
        #pragma unroll
        for (int nt = 0; nt < 4; nt++)
            #pragma unroll
            for (int q = 0; q < 4; q++) c[mt][nt][q] = 0.f;

    for (int stage = 0; stage < 8; stage++) {
        const int ks0 = stage * 16;
        #pragma unroll
        for (int it = 0; it < 2; it++) {
            int f = tid + it * 256;          // 0..511
            int row = f >> 2;
            int kq = f & 3;
            int grow = blockRow + row;
            float4 v = make_float4(0.f, 0.f, 0.f, 0.f);
            if (grow < nrows)
                v = *(const float4*)&h[grow * DFEAT + ks0 + kq * 4];
            float2* dst = &Hs[row * HS_STRIDE + kq * 4];
            float hx = __uint_as_float(__float_as_uint(v.x) & 0xFFFFE000u);
            float hy = __uint_as_float(__float_as_uint(v.y) & 0xFFFFE000u);
            float hz = __uint_as_float(__float_as_uint(v.z) & 0xFFFFE000u);
            float hw = __uint_as_float(__float_as_uint(v.w) & 0xFFFFE000u);
            ((float4*)dst)[0] = make_float4(hx, v.x - hx, hy, v.y - hy);
            ((float4*)dst)[1] = make_float4(hz, v.z - hz, hw, v.w - hw);
        }
        #pragma unroll
        for (int it = 0; it < 4; it++) {
            int f = tid + it * 256;          // 0..1023
            int n = f >> 3;
            int q = f & 7;
            float4 v = *(const float4*)&Wp2[n * DFEAT + ks0 + q * 2];
            *(float4*)&Ws[n * HS_STRIDE + q * 2] = v;
        }
        __syncthreads();

        #pragma unroll
        for (int ks = 0; ks < 2; ks++) {
            const int K0 = ks * 8;
            uint32_t ah[4][4], al[4][4];
            #pragma unroll
            for (int mt = 0; mt < 4; mt++) {
                int base = (M0w + mt * 16 + g) * HS_STRIDE + K0 + tg;
                float2 v0 = Hs[base];
                float2 v1 = Hs[base + 8 * HS_STRIDE];
                float2 v2 = Hs[base + 4];
                float2 v3 = Hs[base + 8 * HS_STRIDE + 4];
                ah[mt][0] = __float_as_uint(v0.x); al[mt][0] = __float_as_uint(v0.y);
                ah[mt][1] = __float_as_uint(v1.x); al[mt][1] = __float_as_uint(v1.y);
                ah[mt][2] = __float_as_uint(v2.x); al[mt][2] = __float_as_uint(v2.y);
                ah[mt][3] = __float_as_uint(v3.x); al[mt][3] = __float_as_uint(v3.y);
            }
            uint32_t bh[4][2], bl[4][2];
            #pragma unroll
            for (int nt = 0; nt < 4; nt++) {
                int base = (N0w + nt * 8 + g) * HS_STRIDE + K0 + tg;
                float2 v0 = Ws[base];
                float2 v1 = Ws[base + 4];
                bh[nt][0] = __float_as_uint(v0.x); bl[nt][0] = __float_as_uint(v0.y);
                bh[nt][1] = __float_as_uint(v1.x); bl[nt][1] = __float_as_uint(v1.y);
            }
            #pragma unroll
            for (int mt = 0; mt < 4; mt++)
                #pragma unroll
                for (int nt = 0; nt < 4; nt++) {
                    mma_tf32(c[mt][nt], ah[mt], bh[nt][0], bh[nt][1]);
                    mma_tf32(c[mt][nt], ah[mt], bl[nt][0], bl[nt][1]);
                    mma_tf32(c[mt][nt], al[mt], bh[nt][0], bh[nt][1]);
                }
        }
        __syncthreads();
    }

    // epilogue: relu(c + bias) -> fp16 and/or fp32
    #pragma unroll
    for (int mt = 0; mt < 4; mt++) {
        int row0 = blockRow + M0w + mt * 16 + g;
        int row1 = row0 + 8;
        #pragma unroll
        for (int nt = 0; nt < 4; nt++) {
            int colj = N0w + nt * 8 + 2 * tg;
            float2 bv = *(const float2*)&bias[colj];
            float2 o0, o1;
            o0.x = fmaxf(c[mt][nt][0] + bv.x, 0.f);
            o0.y = fmaxf(c[mt][nt][1] + bv.y, 0.f);
            o1.x = fmaxf(c[mt][nt][2] + bv.x, 0.f);
            o1.y = fmaxf(c[mt][nt][3] + bv.y, 0.f);
            if (row0 < nrows) {
                if (out16) {
                    __half2 hv = __floats2half2_rn(o0.x, o0.y);
                    *(__half2*)&out16[row0 * DFEAT + colj] = hv;
                }
                if (out32) *(float2*)&out32[row0 * DFEAT + colj] = o0;
            }
            if (row1 < nrows) {
                if (out16) {
                    __half2 hv = __floats2half2_rn(o1.x, o1.y);
                    *(__half2*)&out16[row1 * DFEAT + colj] = hv;
                }
                if (out32) *(float2*)&out32[row1 * DFEAT + colj] = o1;
            }
        }
    }
}

// ---------------- stats / output kernels ----------------

__global__ void colstats_kernel(const float* __restrict__ f, double* __restrict__ sum,
                                double* __restrict__ sumsq, int n) {
    __shared__ double ss[256];
    __shared__ double ss2[256];
    int col = threadIdx.x & 127;
    int half = threadIdx.x >> 7;
    double s = 0.0, s2 = 0.0;
    for (int r = blockIdx.x * 2 + half; r < n; r += gridDim.x * 2) {
        float v = f[r * DFEAT + col];
        s += (double)v;
        s2 += (double)v * (double)v;
    }
    ss[threadIdx.x] = s;
    ss2[threadIdx.x] = s2;
    __syncthreads();
    if (half == 0) {
        atomicAdd(&sum[col], ss[threadIdx.x] + ss[threadIdx.x + 128]);
        atomicAdd(&sumsq[col], ss2[threadIdx.x] + ss2[threadIdx.x + 128]);
    }
}

__global__ void finalize_kernel(const double* __restrict__ sum, const double* __restrict__ sumsq,
                                float* __restrict__ mean, float* __restrict__ rstd, int n) {
    int i = threadIdx.x;
    if (i < 256) {
        double s = sum[i], s2 = sumsq[i];
        double m = s / (double)n;
        double var = (s2 - s * s / (double)n) / (double)(n - 1);
        double sd = sqrt(fmax(var, 0.0));
        sd = fmax(sd, 1e-12);
        mean[i] = (float)m;
        rstd[i] = (float)(1.0 / sd);
    }
}

__global__ void writeout2_kernel(const float* __restrict__ fA, const float* __restrict__ fB,
                                 const float* __restrict__ mean, const float* __restrict__ rstd,
                                 float* __restrict__ out, int n) {
    const float* f = blockIdx.y ? fB : fA;
    int soff4 = blockIdx.y * 32;
    float* o_base = out + (size_t)blockIdx.y * n * DFEAT;
    int idx = blockIdx.x * blockDim.x + threadIdx.x;
    if (idx >= n * 32) return;
    int c4 = idx & 31;
    float4 v = ((const float4*)f)[idx];
    float4 m = ((const float4*)mean)[soff4 + c4];
    float4 r = ((const float4*)rstd)[soff4 + c4];
    float4 o;
    o.x = (v.x - m.x) * r.x;
    o.y = (v.y - m.y) * r.y;
    o.z = (v.z - m.z) * r.z;
    o.w = (v.w - m.w) * r.w;
    ((float4*)o_base)[idx] = o;
}

// ---------------- host launcher ----------------

static void* sym_addr(const void* symbol) {
    void* p = nullptr;
    cudaGetSymbolAddress(&p, symbol);
    return p;
}

extern "C" void kernel_launch(void* const* d_in, const int* in_sizes, int n_in,
                              void* d_out, int out_size) {
    const float* feat1   = (const float*)d_in[0];
    const float* feat2   = (const float*)d_in[1];
    const int*   src1    = (const int*)d_in[2];
    const int*   dst1    = (const int*)d_in[3];
    const int*   src2    = (const int*)d_in[4];
    const int*   dst2    = (const int*)d_in[5];
    const float* weights = (const float*)d_in[6];
    const float* biases  = (const float*)d_in[7];
    const int E1 = in_sizes[2];
    const int E2 = in_sizes[4];
    const int N = NNODES;
    const int L = in_sizes[7] / DFEAT;

    float*  p_h1    = (float*)sym_addr(g_h1);
    float*  p_h2    = (float*)sym_addr(g_h2);
    float*  p_f1    = (float*)sym_addr(g_f1);
    float*  p_f2    = (float*)sym_addr(g_f2);
    __half* p_hf1   = (__half*)sym_addr(g_hf1);
    __half* p_hf2   = (__half*)sym_addr(g_hf2);
    float2* p_wp2   = (float2*)sym_addr(g_wp2);
    int*    p_col1  = (int*)sym_addr(g_col1);
    int*    p_col2  = (int*)sym_addr(g_col2);
    int*    p_deg1  = (int*)sym_addr(g_deg1);
    int*    p_deg2  = (int*)sym_addr(g_deg2);
    int*    p_ps1   = (int*)sym_addr(g_psum1);
    int*    p_ps2   = (int*)sym_addr(g_psum2);
    int*    p_rp1   = (int*)sym_addr(g_rowptr1);
    int*    p_rp2   = (int*)sym_addr(g_rowptr2);
    int*    p_cur1  = (int*)sym_addr(g_cursor1);
    int*    p_cur2  = (int*)sym_addr(g_cursor2);
    float*  p_norm1 = (float*)sym_addr(g_norm1);
    float*  p_norm2 = (float*)sym_addr(g_norm2);
    double* p_sum   = (double*)sym_addr(g_sum);
    double* p_sq    = (double*)sym_addr(g_sumsq);
    float*  p_mean  = (float*)sym_addr(g_mean);
    float*  p_rstd  = (float*)sym_addr(g_rstd);

    static cudaStream_t s2 = nullptr;
    static cudaEvent_t evFork = nullptr, evJoin = nullptr;
    if (s2 == nullptr) {
        cudaStreamCreateWithFlags(&s2, cudaStreamNonBlocking);
        cudaEventCreateWithFlags(&evFork, cudaEventDisableTiming);
        cudaEventCreateWithFlags(&evJoin, cudaEventDisableTiming);
    }
    cudaStream_t s0 = 0;  // legacy default stream (what the harness captures)

    // ---- pre-fork (s0): zero + W' ----
    zero_kernel<<<(N + 255) / 256, 256, 0, s0>>>(p_deg1, p_deg2, p_sum, p_sq, N);
    {
        dim3 grid((DFEAT * DFEAT + 255) / 256, L);
        wprime2_kernel<<<grid, 256, 0, s0>>>(weights, p_wp2);
    }

    // ---- fork ----
    cudaEventRecord(evFork, s0);
    cudaStreamWaitEvent(s2, evFork, 0);

    const int agg_blocks = (N * 32 + 255) / 256;
    const int gemm_blocks = (N + 127) / 128;
    const int n4 = N * DFEAT / 4;
    const int th_blocks = (n4 + 255) / 256;

    // ---- chain for graph 1 on s0 ----
    tohalf_kernel<<<th_blocks, 256, 0, s0>>>(feat1, p_hf1, n4);
    hist_kernel<<<(E1 + 255) / 256, 256, 0, s0>>>(dst1, p_deg1, E1);
    scan_partial_kernel<<<SCAN_BLOCKS, 256, 0, s0>>>(p_deg1, p_ps1, N);
    scan_apply_kernel<<<SCAN_BLOCKS, 256, 0, s0>>>(p_deg1, p_ps1, p_rp1, p_cur1, p_norm1, N);
    fill_kernel<<<(E1 + 255) / 256, 256, 0, s0>>>(src1, dst1, p_cur1, p_col1, E1);
    for (int l = 0; l < L; l++) {
        const float2* Wl = p_wp2 + (size_t)l * DFEAT * DFEAT;
        const float* bl = biases + (size_t)l * DFEAT;
        bool last = (l == L - 1);
        aggregate_h_kernel<<<agg_blocks, 256, 0, s0>>>(p_hf1, feat1, p_norm1, p_rp1, p_col1, p_h1, N);
        gemm_tc_kernel<<<gemm_blocks, 256, 0, s0>>>(p_h1, last ? nullptr : p_hf1,
                                                    last ? p_f1 : nullptr, Wl, bl, N);
    }
    colstats_kernel<<<256, 256, 0, s0>>>(p_f1, p_sum, p_sq, N);

    // ---- chain for graph 2 on s2 ----
    tohalf_kernel<<<th_blocks, 256, 0, s2>>>(feat2, p_hf2, n4);
    hist_kernel<<<(E2 + 255) / 256, 256, 0, s2>>>(dst2, p_deg2, E2);
    scan_partial_kernel<<<SCAN_BLOCKS, 256, 0, s2>>>(p_deg2, p_ps2, N);
    scan_apply_kernel<<<SCAN_BLOCKS, 256, 0, s2>>>(p_deg2, p_ps2, p_rp2, p_cur2, p_norm2, N);
    fill_kernel<<<(E2 + 255) / 256, 256, 0, s2>>>(src2, dst2, p_cur2, p_col2, E2);
    for (int l = 0; l < L; l++) {
        const float2* Wl = p_wp2 + (size_t)l * DFEAT * DFEAT;
        const float* bl = biases + (size_t)l * DFEAT;
        bool last = (l == L - 1);
        aggregate_h_kernel<<<agg_blocks, 256, 0, s2>>>(p_hf2, feat2, p_norm2, p_rp2, p_col2, p_h2, N);
        gemm_tc_kernel<<<gemm_blocks, 256, 0, s2>>>(p_h2, last ? nullptr : p_hf2,
                                                    last ? p_f2 : nullptr, Wl, bl, N);
    }
    colstats_kernel<<<256, 256, 0, s2>>>(p_f2, p_sum + 128, p_sq + 128, N);

    // ---- join ----
    cudaEventRecord(evJoin, s2);
    cudaStreamWaitEvent(s0, evJoin, 0);

    // ---- finalize + writeout ----
    finalize_kernel<<<1, 256, 0, s0>>>(p_sum, p_sq, p_mean, p_rstd, N);
    {
        dim3 grid((N * 32 + 255) / 256, 2);
        writeout2_kernel<<<grid, 256, 0, s0>>>(p_f1, p_f2, p_mean, p_rstd, (float*)d_out, N);
    }
}